// round 5
// baseline (speedup 1.0000x reference)
#include <cuda_runtime.h>
#include <cstdint>

// ---------------------------------------------------------------------------
// QuadConv via baseline-PTX tf32 mma.sync (harness virtual arch = compute_103:
// no tcgen05/TMEM/'a'-suffix features survive ptxas).
//
//   out[N,128] = concat_k( F[idx[:,k]] ) @ W^T + b
//   N=262144, C_IN=128, C_OUT=128, K=9  ->  GEMM M=N, N=128, K=1152,
//   A rows gathered.
//
// NOTE: neigh_idx is int32 on the wire (JAX x64 disabled downgrades the
// reference's jnp.int64 to int32). Reading it as int64 was the R3 crash.
//
// CTA: 512 thr (16 warps, 4x4), tile 256x128, warp tile 64x32.
// K-loop: 36 blocks of 32, double-buffered cp.async for A and B.
// ---------------------------------------------------------------------------

namespace qc {
constexpr int NPTS   = 262144;
constexpr int CIN    = 128;
constexpr int COUT   = 128;
constexpr int KNB    = 9;
constexpr int KTOT   = KNB * CIN;      // 1152
constexpr int NKB    = KTOT / 32;      // 36 k-blocks of 32
constexpr int MTILE  = 256;
constexpr int CTAS   = NPTS / MTILE;   // 1024
constexpr int THREADS = 512;

constexpr int ROWPAD = 36;             // floats per smem row (32 + 4 pad)
// smem layout (in floats)
constexpr int A_FLOATS   = MTILE * ROWPAD;      // 9216 per buffer
constexpr int B_FLOATS   = COUT * ROWPAD;       // 4608 per buffer
constexpr int OFF_A      = 0;                   // 2 buffers
constexpr int OFF_B      = 2 * A_FLOATS;        // 18432, 2 buffers
constexpr int OFF_IDX    = OFF_B + 2 * B_FLOATS;          // 27648 (ints)
constexpr int OFF_BIAS   = OFF_IDX + KNB * MTILE;         // 29952
constexpr int SMEM_FLOATS = OFF_BIAS + COUT;              // 30080
constexpr int SMEM_BYTES  = SMEM_FLOATS * 4;              // 120320
} // namespace qc

// ------------------------------ PTX helpers -------------------------------

__device__ __forceinline__ uint32_t smem_u32(const void* p) {
    return (uint32_t)__cvta_generic_to_shared(p);
}

__device__ __forceinline__ void cp_async16(uint32_t dst, const void* src, int src_size) {
    asm volatile("cp.async.cg.shared.global [%0], [%1], 16, %2;"
                 ::"r"(dst), "l"(src), "r"(src_size) : "memory");
}
__device__ __forceinline__ void cp_commit() {
    asm volatile("cp.async.commit_group;" ::: "memory");
}
template <int N>
__device__ __forceinline__ void cp_wait() {
    asm volatile("cp.async.wait_group %0;" ::"n"(N) : "memory");
}

__device__ __forceinline__ uint32_t f2tf32(float f) {
    uint32_t u;
    asm("cvt.rna.tf32.f32 %0, %1;" : "=r"(u) : "f"(f));
    return u;
}

__device__ __forceinline__ void mma_tf32(float& c0, float& c1, float& c2, float& c3,
                                         uint32_t a0, uint32_t a1, uint32_t a2, uint32_t a3,
                                         uint32_t b0, uint32_t b1) {
    asm volatile(
        "mma.sync.aligned.m16n8k8.row.col.f32.tf32.tf32.f32 "
        "{%0,%1,%2,%3}, {%4,%5,%6,%7}, {%8,%9}, {%0,%1,%2,%3};"
        : "+f"(c0), "+f"(c1), "+f"(c2), "+f"(c3)
        : "r"(a0), "r"(a1), "r"(a2), "r"(a3), "r"(b0), "r"(b1));
}

// ------------------------------- kernel -----------------------------------

__global__ void __launch_bounds__(qc::THREADS, 1)
quadconv_mma_kernel(const float* __restrict__ F,
                    const int* __restrict__ NIDX,      // int32 on the wire!
                    const float* __restrict__ W,
                    const float* __restrict__ BIAS,
                    float* __restrict__ OUT) {
    using namespace qc;
    extern __shared__ float sm[];
    float* sA    = sm + OFF_A;                 // [2][256][36]
    float* sB    = sm + OFF_B;                 // [2][128][36]
    int*   sidx  = (int*)(sm + OFF_IDX);       // [9][256]
    float* sbias = sm + OFF_BIAS;              // [128]

    const uint32_t sA_u = smem_u32(sA);
    const uint32_t sB_u = smem_u32(sB);

    const int tid  = threadIdx.x;
    const int wid  = tid >> 5;
    const int lane = tid & 31;
    const int g    = lane >> 2;   // 0..7
    const int klo  = lane & 3;    // 0..3
    const int gb   = blockIdx.x * MTILE;

    // ---- stage neighbor indices (int32) and bias ---------------------------
    for (int e = tid; e < KNB * MTILE; e += THREADS) {
        int row = e / KNB, kn = e % KNB;
        sidx[kn * MTILE + row] = NIDX[(size_t)(gb + row) * KNB + kn];
    }
    if (tid < COUT) sbias[tid] = BIAS[tid];
    __syncthreads();

    // ---- tile loader: A gather (zfill for out-of-range) + B (W chunk) -----
    auto load_tiles = [&](int kb, int buf) {
        const int kn   = kb >> 2;             // neighbor 0..8
        const int coff = (kb & 3) * 32;       // col offset within feature row
        const int* idxp = sidx + kn * MTILE;
#pragma unroll
        for (int i = 0; i < 4; i++) {         // A: 2048 chunks / 512 thr
            int e = tid + i * THREADS;
            int row = e >> 3, seg = e & 7;
            int nb  = idxp[row];
            bool ok = (unsigned)nb < (unsigned)NPTS;   // -1 (or junk) -> zeros
            const float* src = F + (size_t)(ok ? nb : 0) * CIN + coff + seg * 4;
            cp_async16(sA_u + (uint32_t)(buf * A_FLOATS + row * ROWPAD + seg * 4) * 4,
                       src, ok ? 16 : 0);
        }
#pragma unroll
        for (int i = 0; i < 2; i++) {         // B: 1024 chunks / 512 thr
            int e = tid + i * THREADS;
            int n = e >> 3, seg = e & 7;
            const float* src = W + (size_t)n * KTOT + kb * 32 + seg * 4;
            cp_async16(sB_u + (uint32_t)(buf * B_FLOATS + n * ROWPAD + seg * 4) * 4,
                       src, 16);
        }
    };

    // ---- accumulators: warp tile 64(M) x 32(N) -> 4 mfrags x 4 nfrags -----
    const int Mbase = (wid >> 2) * 64;
    const int Nbase = (wid & 3) * 32;
    float acc[4][4][4];
#pragma unroll
    for (int mf = 0; mf < 4; mf++)
#pragma unroll
        for (int nf = 0; nf < 4; nf++)
#pragma unroll
            for (int q = 0; q < 4; q++) acc[mf][nf][q] = 0.f;

    // ---- prologue ----------------------------------------------------------
    load_tiles(0, 0);
    cp_commit();

    // ---- main K loop -------------------------------------------------------
    for (int kb = 0; kb < NKB; kb++) {
        const int buf = kb & 1;
        if (kb + 1 < NKB) {
            load_tiles(kb + 1, buf ^ 1);
            cp_commit();
            cp_wait<1>();
        } else {
            cp_wait<0>();
        }
        __syncthreads();

        const float* A = sA + buf * A_FLOATS;
        const float* B = sB + buf * B_FLOATS;

#pragma unroll
        for (int s = 0; s < 4; s++) {         // 4 k-steps of 8
            uint32_t afr[4][4];
#pragma unroll
            for (int mf = 0; mf < 4; mf++) {
                int base = (Mbase + mf * 16 + g) * ROWPAD + s * 8 + klo;
                afr[mf][0] = f2tf32(A[base]);
                afr[mf][1] = f2tf32(A[base + 8 * ROWPAD]);
                afr[mf][2] = f2tf32(A[base + 4]);
                afr[mf][3] = f2tf32(A[base + 8 * ROWPAD + 4]);
            }
            uint32_t bfr[4][2];
#pragma unroll
            for (int nf = 0; nf < 4; nf++) {
                int base = (Nbase + nf * 8 + g) * ROWPAD + s * 8 + klo;
                bfr[nf][0] = f2tf32(B[base]);
                bfr[nf][1] = f2tf32(B[base + 4]);
            }
#pragma unroll
            for (int mf = 0; mf < 4; mf++)
#pragma unroll
                for (int nf = 0; nf < 4; nf++)
                    mma_tf32(acc[mf][nf][0], acc[mf][nf][1],
                             acc[mf][nf][2], acc[mf][nf][3],
                             afr[mf][0], afr[mf][1], afr[mf][2], afr[mf][3],
                             bfr[nf][0], bfr[nf][1]);
        }
        __syncthreads();   // all reads of buf done before kb+2 overwrites it
    }

    // ---- epilogue: add bias, float2 stores (32B-sector coalesced) ----------
#pragma unroll
    for (int mf = 0; mf < 4; mf++) {
#pragma unroll
        for (int nf = 0; nf < 4; nf++) {
            int col  = Nbase + nf * 8 + 2 * klo;
            float bx = sbias[col], by = sbias[col + 1];
            size_t r0 = (size_t)(gb + Mbase + mf * 16 + g) * COUT + col;
            size_t r1 = r0 + (size_t)8 * COUT;
            float2 v0 = make_float2(acc[mf][nf][0] + bx, acc[mf][nf][1] + by);
            float2 v1 = make_float2(acc[mf][nf][2] + bx, acc[mf][nf][3] + by);
            *(float2*)(OUT + r0) = v0;
            *(float2*)(OUT + r1) = v1;
        }
    }
}

// ----------------------------- launch glue --------------------------------

extern "C" void kernel_launch(void* const* d_in, const int* in_sizes, int n_in,
                              void* d_out, int out_size) {
    using namespace qc;
    const float* F = (const float*)d_in[0];
    const int*   I = (const int*)d_in[1];
    const float* W = (const float*)d_in[2];
    const float* B = (const float*)d_in[3];
    for (int i = 0; i < n_in; i++) {
        switch (in_sizes[i]) {
            case NPTS * CIN:       F = (const float*)d_in[i]; break;      // 33554432
            case NPTS * KNB:       I = (const int*)d_in[i];   break;      // 2359296
            case COUT * KNB * CIN: W = (const float*)d_in[i]; break;      // 147456
            case COUT:             B = (const float*)d_in[i]; break;      // 128
            default: break;
        }
    }
    cudaFuncSetAttribute(quadconv_mma_kernel,
                         cudaFuncAttributeMaxDynamicSharedMemorySize, SMEM_BYTES);
    quadconv_mma_kernel<<<CTAS, THREADS, SMEM_BYTES>>>(F, I, W, B, (float*)d_out);
}